// round 11
// baseline (speedup 1.0000x reference)
#include <cuda_runtime.h>
#include <math.h>

namespace {
constexpr int B_ = 32, L_ = 32, D_ = 512, H_ = 512;
constexpr int H2_ = 1024, H5_ = 2560;
constexpr int PSLOT = 64, ZSLOT = 63;   // pool slots per batch; 63 = zero slot
constexpr int CSLOT = 96, DSLOT = 95;   // cache slots per batch; 95 = dummy
constexpr int NCTA = 148;               // persistent grid == SM count -> always co-resident
}

typedef unsigned long long u64;

__device__ __align__(16) float g_poolH[B_ * PSLOT * H_];
__device__ __align__(16) float g_poolC[B_ * PSLOT * H_];
__device__ __align__(16) float g_uL[B_ * PSLOT * H5_];
__device__ __align__(16) float g_uR[B_ * PSLOT * H5_];
__device__ __align__(16) float g_cacheH[B_ * CSLOT * H_];
__device__ __align__(16) float g_cacheC[B_ * CSLOT * H_];
__device__ float g_logit[B_ * CSLOT];
__device__ int4  g_tasks[2 * B_];
__device__ int   g_newSlot[B_];
__device__ int   g_slotOf[B_ * L_];
__device__ int   g_cidx[B_ * L_];
__device__ int2  g_mlist[1024];
__device__ int   g_mcount;
__device__ unsigned g_barCnt[64];

__device__ __forceinline__ float sigm(float x) { return 1.f / (1.f + expf(-x)); }

#define FFMA2(d, a, b) asm("fma.rn.f32x2 %0, %1, %2, %0;" : "+l"(d) : "l"(a), "l"(b))
__device__ __forceinline__ u64 pk2(float lo, float hi) {
    u64 r; asm("mov.b64 %0, {%1, %2};" : "=l"(r) : "f"(lo), "f"(hi)); return r;
}
__device__ __forceinline__ float2 up2(u64 p) {
    float2 r; asm("mov.b64 {%0, %1}, %2;" : "=f"(r.x), "=f"(r.y) : "l"(p)); return r;
}

__device__ __forceinline__ void gridBar(int id) {
    __syncthreads();
    if (threadIdx.x == 0) {
        __threadfence();
        atomicAdd(&g_barCnt[id], 1u);
        while (*(volatile unsigned*)&g_barCnt[id] < (unsigned)NCTA) {}
        __threadfence();
    }
    __syncthreads();
}

// ---------------------------------------------------------------------------
__global__ void kInit(const int* __restrict__ len) {
    int t = blockIdx.x * blockDim.x + threadIdx.x;   // 4096 threads
    if (t < 64) g_barCnt[t] = 0u;
    if (t < B_ * L_) {
        int p = t % L_;
        g_slotOf[t] = p;
        g_cidx[t]   = (p < L_ - 1) ? p : DSLOT;
    }
    if (t < B_) g_logit[t * CSLOT + DSLOT] = 0.f;
    if (blockIdx.x == 0 && threadIdx.x < B_) {
        // compacted u-row list: slots 0..min(lb,31) per batch (slot lb is the
        // single garbage leaf any consumer reads).
        int b = threadIdx.x, off = 0;
        for (int j = 0; j < b; j++) {
            int c = len[j] + 1; if (c > 32) c = 32; off += c;
        }
        int c = len[b] + 1; if (c > 32) c = 32;
        for (int j = 0; j < c; j++) g_mlist[off + j] = make_int2(b, j);
        if (b == B_ - 1) g_mcount = off + c;
    }
    for (int i = t; i < B_ * H_; i += 4096) {
        int b = i / H_, j = i % H_;
        g_poolH[(b * PSLOT + ZSLOT) * H_ + j] = 0.f;
        g_poolC[(b * PSLOT + ZSLOT) * H_ + j] = 0.f;
        g_cacheH[(b * CSLOT + DSLOT) * H_ + j] = 0.f;
        g_cacheC[(b * CSLOT + DSLOT) * H_ + j] = 0.f;
    }
    for (int i = t; i < B_ * H5_; i += 4096) {
        int b = i / H5_, j = i % H5_;
        g_uL[(b * PSLOT + ZSLOT) * H5_ + j] = 0.f;
        g_uR[(b * PSLOT + ZSLOT) * H5_ + j] = 0.f;
    }
}

// ---------------------------------------------------------------------------
// 64x128 GEMM core, 256 threads, 4 rows x 8 cols per thread (f32x2 packed,
// conflict-free/broadcast LDS). High warp count for latency hiding.
// aPtr = A-row (m0 + tid/4) base + (tid&3)*4.
// bPtr = W + (tid>>4)*ldb + n0 + (tid&15)*4.
// ---------------------------------------------------------------------------
__device__ __forceinline__ void gemm256core(const float* aPtr, const float* bPtr,
                                            int ldb, int K, int tid,
                                            float (*Xs)[68], float (*Ws)[132],
                                            u64 (*acc)[4]) {
    const int ar = tid >> 2, aq = (tid & 3) * 4;
    const int wr = tid >> 4, wc = tid & 15;
    const int ty = tid >> 4, tx = tid & 15;
    float4 xa  = *(const float4*)(aPtr);
    float4 wv0 = *(const float4*)(bPtr);
    float4 wv1 = *(const float4*)(bPtr + 64);
    for (int k0 = 0; k0 < K; k0 += 16) {
        Xs[aq+0][ar] = xa.x; Xs[aq+1][ar] = xa.y;
        Xs[aq+2][ar] = xa.z; Xs[aq+3][ar] = xa.w;
        *(float4*)&Ws[wr][wc*4]      = wv0;
        *(float4*)&Ws[wr][wc*4 + 64] = wv1;
        __syncthreads();
        if (k0 + 16 < K) {
            xa  = *(const float4*)(aPtr + k0 + 16);
            const float* bn = bPtr + (k0 + 16) * ldb;
            wv0 = *(const float4*)(bn);
            wv1 = *(const float4*)(bn + 64);
        }
#pragma unroll
        for (int kk = 0; kk < 16; kk++) {
            float4 a = *(const float4*)&Xs[kk][ty*4];
            u64 pa0 = pk2(a.x,a.x), pa1 = pk2(a.y,a.y);
            u64 pa2 = pk2(a.z,a.z), pa3 = pk2(a.w,a.w);
            u64 bb0 = *(const u64*)&Ws[kk][tx*2];
            u64 bb1 = *(const u64*)&Ws[kk][32 + tx*2];
            u64 bb2 = *(const u64*)&Ws[kk][64 + tx*2];
            u64 bb3 = *(const u64*)&Ws[kk][96 + tx*2];
            FFMA2(acc[0][0],pa0,bb0); FFMA2(acc[0][1],pa0,bb1); FFMA2(acc[0][2],pa0,bb2); FFMA2(acc[0][3],pa0,bb3);
            FFMA2(acc[1][0],pa1,bb0); FFMA2(acc[1][1],pa1,bb1); FFMA2(acc[1][2],pa1,bb2); FFMA2(acc[1][3],pa1,bb3);
            FFMA2(acc[2][0],pa2,bb0); FFMA2(acc[2][1],pa2,bb1); FFMA2(acc[2][2],pa2,bb2); FFMA2(acc[2][3],pa2,bb3);
            FFMA2(acc[3][0],pa3,bb0); FFMA2(acc[3][1],pa3,bb1); FFMA2(acc[3][2],pa3,bb2); FFMA2(acc[3][3],pa3,bb3);
        }
        __syncthreads();
    }
}

// ---------------------------------------------------------------------------
// Leaf GEMM: hc = inp @ W_word + b_word. M=1024, N=1024, K=512. grid(16,8),256thr.
// ---------------------------------------------------------------------------
__global__ void __launch_bounds__(256) kLeafGemm(const float* __restrict__ inp,
                                                 const float* __restrict__ Ww,
                                                 const float* __restrict__ bw,
                                                 float* __restrict__ nodes) {
    const int m0 = blockIdx.x * 64, n0 = blockIdx.y * 128;
    __shared__ __align__(16) float Xs[16][68];
    __shared__ __align__(16) float Ws[16][132];
    const int tid = threadIdx.x;
    u64 acc[4][4] = {};
    const float* aPtr = inp + (m0 + (tid >> 2)) * D_ + (tid & 3) * 4;
    const float* bPtr = Ww + (tid >> 4) * H2_ + n0 + (tid & 15) * 4;
    gemm256core(aPtr, bPtr, H2_, D_, tid, Xs, Ws, acc);

    const int ty = tid >> 4, tx = tid & 15;
    const int cHalf = (n0 >= H_) ? 1 : 0;
#pragma unroll
    for (int r = 0; r < 4; r++) {
        int m = m0 + ty * 4 + r, b = m / L_, l = m % L_;
#pragma unroll
        for (int p = 0; p < 4; p++) {
            int n = n0 + 32 * p + tx * 2;
            float2 bias = *(const float2*)(bw + n);
            float2 v = up2(acc[r][p]);
            v.x += bias.x; v.y += bias.y;
            if (!cHalf) {
                *(float2*)&g_poolH[(b * PSLOT + l) * H_ + n] = v;
                *(float2*)&nodes[(b * 63 + l) * H_ + n] = v;
            } else {
                *(float2*)&g_poolC[(b * PSLOT + l) * H_ + (n - H_)] = v;
            }
        }
    }
}

// ---------------------------------------------------------------------------
// Compacted front u-GEMM (one half): M=g_mcount rows, N=2560, K=512.
// grid(16, 20), 256 thr; blocks with m0 >= cnt exit.
// ---------------------------------------------------------------------------
__global__ void __launch_bounds__(256) kUGemmHalf(const float* __restrict__ Wc,
                                                  int half) {
    const int cnt = g_mcount;
    const int m0 = blockIdx.x * 64;
    if (m0 >= cnt) return;
    const int nn = blockIdx.y * 128;
    __shared__ __align__(16) float Xs[16][68];
    __shared__ __align__(16) float Ws[16][132];
    __shared__ int2 sRows[64];
    const int tid = threadIdx.x;
    if (tid < 64) {
        int r = m0 + tid; if (r >= cnt) r = cnt - 1;
        sRows[tid] = g_mlist[r];
    }
    __syncthreads();
    u64 acc[4][4] = {};
    int2 me = sRows[tid >> 2];
    const float* aPtr = g_poolH + (me.x * PSLOT + me.y) * H_ + (tid & 3) * 4;
    const float* bPtr = Wc + (half * H_ + (tid >> 4)) * H5_ + nn + (tid & 15) * 4;
    gemm256core(aPtr, bPtr, H5_, H_, tid, Xs, Ws, acc);

    const int ty = tid >> 4, tx = tid & 15;
    float* U = half ? g_uR : g_uL;
#pragma unroll
    for (int r = 0; r < 4; r++) {
        int row = m0 + ty * 4 + r;
        if (row < cnt) {
            int2 e = sRows[ty * 4 + r];
            float* dst = U + (e.x * PSLOT + e.y) * H5_ + nn;
#pragma unroll
            for (int p = 0; p < 4; p++)
                *(float2*)&dst[32 * p + tx * 2] = up2(acc[r][p]);
        }
    }
}

// ---------------------------------------------------------------------------
// Vectorized pair activation: lt in [0,128), each thread does 4 elements.
// ---------------------------------------------------------------------------
__device__ __forceinline__ void actPair4(int b, int ls, int rs, int cs,
                                         const float* __restrict__ bc,
                                         const float* __restrict__ q,
                                         int lt, float* red) {
    const float* ul = g_uL + (b * PSLOT + ls) * H5_;
    const float* ur = g_uR + (b * PSLOT + rs) * H5_;
    const float* cl = g_poolC + (b * PSLOT + ls) * H_;
    const float* cr = g_poolC + (b * PSLOT + rs) * H_;
    float* oh = g_cacheH + (b * CSLOT + cs) * H_;
    float* oc = g_cacheC + (b * CSLOT + cs) * H_;
    int j = lt * 4;
    float G[5][4];
#pragma unroll
    for (int g = 0; g < 5; g++) {
        float4 a = *(const float4*)(ul + g * H_ + j);
        float4 r = *(const float4*)(ur + g * H_ + j);
        float4 c = *(const float4*)(bc + g * H_ + j);
        G[g][0] = a.x + r.x + c.x; G[g][1] = a.y + r.y + c.y;
        G[g][2] = a.z + r.z + c.z; G[g][3] = a.w + r.w + c.w;
    }
    float4 cl4 = *(const float4*)(cl + j);
    float4 cr4 = *(const float4*)(cr + j);
    float4 q4  = *(const float4*)(q + j);
    float clv[4] = {cl4.x, cl4.y, cl4.z, cl4.w};
    float crv[4] = {cr4.x, cr4.y, cr4.z, cr4.w};
    float hv[4], cv[4];
#pragma unroll
    for (int l = 0; l < 4; l++) {
        float c = clv[l] * sigm(G[1][l] + 1.f) + crv[l] * sigm(G[2][l] + 1.f)
                + tanhf(G[3][l]) * sigm(G[0][l]);
        hv[l] = sigm(G[4][l]) * tanhf(c); cv[l] = c;
    }
    *(float4*)(oh + j) = make_float4(hv[0], hv[1], hv[2], hv[3]);
    *(float4*)(oc + j) = make_float4(cv[0], cv[1], cv[2], cv[3]);
    float acc = hv[0]*q4.x + hv[1]*q4.y + hv[2]*q4.z + hv[3]*q4.w;
    for (int o = 16; o > 0; o >>= 1) acc += __shfl_down_sync(0xffffffffu, acc, o);
    if ((lt & 31) == 0) red[lt >> 5] = acc;
    __syncthreads();
    if (lt == 0)
        g_logit[b * CSLOT + cs] = red[0] + red[1] + red[2] + red[3];
}

__global__ void __launch_bounds__(128) kAct0(const int* __restrict__ len,
                                             const float* __restrict__ bc,
                                             const float* __restrict__ q) {
    __shared__ float red[4];
    int b = blockIdx.y, j = blockIdx.x;
    if (j >= len[b] - 1) return;
    actPair4(b, j, j + 1, j, bc, q, threadIdx.x, red);
}

// ---------------------------------------------------------------------------
// Select for batch b at step stepI (direct-store u-GEMM: no zeroing needed).
// ---------------------------------------------------------------------------
__device__ void doSelect(int b, int stepI, const int* __restrict__ len,
                         float* __restrict__ nodes, float* __restrict__ hf,
                         float* __restrict__ cf,
                         int* sPos, int* sPair, int* sKp) {
    int t = threadIdx.x;
    if (t < 32) sPos[t] = g_slotOf[b * L_ + t];
    if (t < 31) sPair[t] = g_cidx[b * L_ + t];
    __syncthreads();
    int lb = len[b];
    if (stepI < lb - 1) {
        if (t == 0) {
            int cand = lb - 1 - stepI, k = 0;
            float best = -1e30f;
            for (int j = 0; j < cand; j++) {
                float v = g_logit[b * CSLOT + sPair[j]];
                if (v > best) { best = v; k = j; }
            }
            *sKp = k;
        }
        __syncthreads();
        int k = *sKp, cs = sPair[k], mslot = 32 + stepI;
        const float* ch = &g_cacheH[(b * CSLOT + cs) * H_];
        const float* cc = &g_cacheC[(b * CSLOT + cs) * H_];
        float* ph = &g_poolH[(b * PSLOT + mslot) * H_];
        float* pc = &g_poolC[(b * PSLOT + mslot) * H_];
        float* nd = &nodes[(b * 63 + 32 + stepI) * H_];
        for (int j = t; j < H_; j += blockDim.x) {
            float hvv = ch[j], cvv = cc[j];
            ph[j] = hvv; pc[j] = cvv; nd[j] = hvv;
            if (stepI == L_ - 2) { hf[b * H_ + j] = hvv; cf[b * H_ + j] = cvv; }
        }
        if (t < 32) {
            int np = (t < k) ? sPos[t] : (t == k) ? mslot : (t < 31) ? sPos[t + 1] : ZSLOT;
            g_slotOf[b * L_ + t] = np;
        }
        if (t < 31) {
            int np;
            if      (t <  k - 1) np = sPair[t];
            else if (t == k - 1) np = 31 + 2 * stepI;
            else if (t == k)     np = 32 + 2 * stepI;
            else if (t < 30)     np = sPair[t + 1];
            else                 np = DSLOT;
            g_cidx[b * L_ + t] = np;
        }
        if (t == 0) {
            int A = 31 + 2 * stepI, Bc = 32 + 2 * stepI;
            g_tasks[2 * b] = (k > 0) ? make_int4(b, sPos[k - 1], mslot, A)
                                     : make_int4(b, ZSLOT, ZSLOT, DSLOT);
            int r = (k + 2 <= 31) ? sPos[k + 2] : ZSLOT;
            g_tasks[2 * b + 1] = make_int4(b, mslot, r, Bc);
            g_newSlot[b] = mslot;
        }
    } else {
        float* nd = &nodes[(b * 63 + 32 + stepI) * H_];
        if (stepI == L_ - 2) {
            int rs = sPos[0];
            const float* ph = &g_poolH[(b * PSLOT + rs) * H_];
            const float* pc = &g_poolC[(b * PSLOT + rs) * H_];
            for (int j = t; j < H_; j += blockDim.x) {
                float hvv = ph[j];
                nd[j] = hvv; hf[b * H_ + j] = hvv; cf[b * H_ + j] = pc[j];
            }
        } else {
            int cs = sPair[0];
            const float* ch = &g_cacheH[(b * CSLOT + cs) * H_];
            for (int j = t; j < H_; j += blockDim.x) nd[j] = ch[j];
        }
        if (t == 0) {
            g_tasks[2 * b]     = make_int4(b, ZSLOT, ZSLOT, DSLOT);
            g_tasks[2 * b + 1] = make_int4(b, ZSLOT, ZSLOT, DSLOT);
            g_newSlot[b] = ZSLOT;
        }
    }
    __syncthreads();
}

// ---------------------------------------------------------------------------
// Persistent loop: NCTA=148 (== SM count: co-residency guaranteed at any reg
// count). select_0, then 30x [u-GEMM (80 CTAs, 64-col full-K tiles, direct
// store) | act+select (32 CTAs)], 148-CTA barriers between phases.
// ---------------------------------------------------------------------------
__global__ void __launch_bounds__(256) kPersist(const int* __restrict__ len,
                                                const float* __restrict__ Wc,
                                                const float* __restrict__ bc,
                                                const float* __restrict__ q,
                                                float* __restrict__ nodes,
                                                float* __restrict__ hf,
                                                float* __restrict__ cf) {
    const int cta = blockIdx.x, tid = threadIdx.x;
    __shared__ __align__(16) float As[16][36];
    __shared__ __align__(16) float Ws[16][68];
    __shared__ int sSlot[32];
    __shared__ int sPos[32], sPair[31], sK;
    __shared__ float red[8];

    if (cta < B_) doSelect(cta, 0, len, nodes, hf, cf, sPos, sPair, &sK);
    gridBar(0);

    const int n0g = cta * 64;
    const int half = (n0g >= H5_) ? 1 : 0;
    const int nn = n0g - half * H5_;
    const int mS = tid >> 2, qS = tid & 3;     // staging (tid<128): rows 0..31
    const int mg = tid >> 4, tx = tid & 15;    // compute: 2 rows, 2 col-pairs
    const float* bPtr0 = Wc + (half * H_ + (tid >> 4)) * H5_ + nn + (tid & 15) * 4;

    for (int i = 1; i <= L_ - 2; i++) {
        if (tid < B_) sSlot[tid] = ((volatile int*)g_newSlot)[tid];
        __syncthreads();
        if (cta < 80) {   // ---- phase 1: u-GEMM, M=32, N=5120, K=512
            const float* aPtr = (tid < 128)
                ? g_poolH + (mS * PSLOT + sSlot[mS]) * H_ + qS * 4 : g_poolH;
            float4 xr, wv;
            if (tid < 128) xr = *(const float4*)aPtr;
            wv = *(const float4*)bPtr0;
            u64 acc[2][2] = {};
            for (int k0 = 0; k0 < H_; k0 += 16) {
                if (tid < 128) {
                    As[qS*4+0][mS] = xr.x; As[qS*4+1][mS] = xr.y;
                    As[qS*4+2][mS] = xr.z; As[qS*4+3][mS] = xr.w;
                }
                *(float4*)&Ws[tid >> 4][(tid & 15) * 4] = wv;
                __syncthreads();
                if (k0 + 16 < H_) {
                    if (tid < 128) xr = *(const float4*)(aPtr + k0 + 16);
                    wv = *(const float4*)(bPtr0 + (k0 + 16) * H5_);
                }
#pragma unroll
                for (int kk = 0; kk < 16; kk++) {
                    float a0 = As[kk][mg * 2], a1 = As[kk][mg * 2 + 1];
                    u64 b01 = *(const u64*)&Ws[kk][tx*2];
                    u64 b23 = *(const u64*)&Ws[kk][32 + tx*2];
                    u64 pa0 = pk2(a0, a0), pa1 = pk2(a1, a1);
                    FFMA2(acc[0][0], pa0, b01); FFMA2(acc[0][1], pa0, b23);
                    FFMA2(acc[1][0], pa1, b01); FFMA2(acc[1][1], pa1, b23);
                }
                __syncthreads();
            }
            float* U = half ? g_uR : g_uL;
#pragma unroll
            for (int e = 0; e < 2; e++) {
                int r = mg * 2 + e;
                float* base = U + (r * PSLOT + sSlot[r]) * H5_ + nn;
                *(float2*)(base + tx * 2)      = up2(acc[e][0]);
                *(float2*)(base + 32 + tx * 2) = up2(acc[e][1]);
            }
        }
        gridBar(2 * i - 1);
        // ---- phase 2: act (2 tasks, warp halves) + select (32 CTAs)
        if (cta < B_) {
            int4 tk = (tid < 128) ? g_tasks[2 * cta] : g_tasks[2 * cta + 1];
            actPair4(cta, tk.y, tk.z, tk.w, bc, q, tid & 127, red + ((tid >> 7) << 2));
            __syncthreads();
            doSelect(cta, i, len, nodes, hf, cf, sPos, sPair, &sK);
        }
        gridBar(2 * i);
    }
}

// ---------------------------------------------------------------------------
extern "C" void kernel_launch(void* const* d_in, const int* in_sizes, int n_in,
                              void* d_out, int out_size) {
    const float* inp = (const float*)d_in[0];
    const int*   len = (const int*)  d_in[1];
    const float* Ww  = (const float*)d_in[2];
    const float* bw  = (const float*)d_in[3];
    const float* Wc  = (const float*)d_in[4];
    const float* bc  = (const float*)d_in[5];
    const float* q   = (const float*)d_in[6];
    float* out   = (float*)d_out;
    float* hf    = out;
    float* cf    = out + B_ * H_;
    float* nodes = out + 2 * B_ * H_;

    kInit<<<16, 256>>>(len);
    kLeafGemm<<<dim3(16, 8), 256>>>(inp, Ww, bw, nodes);
    kUGemmHalf<<<dim3(16, 20), 256>>>(Wc, 0);
    kUGemmHalf<<<dim3(16, 20), 256>>>(Wc, 1);   // <- ncu slot: verify occupancy fix
    kAct0<<<dim3(31, B_), 128>>>(len, bc, q);
    kPersist<<<NCTA, 256>>>(len, Wc, bc, q, nodes, hf, cf);
}

// round 12
// speedup vs baseline: 1.2722x; 1.2722x over previous
#include <cuda_runtime.h>
#include <math.h>

namespace {
constexpr int B_ = 32, L_ = 32, D_ = 512, H_ = 512;
constexpr int H2_ = 1024, H5_ = 2560;
constexpr int PSLOT = 64, ZSLOT = 63;   // pool slots per batch; 63 = zero slot
constexpr int CSLOT = 96, DSLOT = 95;   // cache slots per batch; 95 = dummy
constexpr int NCTA = 160;               // fused step kernel grid (80 x 2)
}

typedef unsigned long long u64;

__device__ __align__(16) float g_poolH[B_ * PSLOT * H_];
__device__ __align__(16) float g_poolC[B_ * PSLOT * H_];
__device__ __align__(16) float g_uL[B_ * PSLOT * H5_];
__device__ __align__(16) float g_uR[B_ * PSLOT * H5_];
__device__ __align__(16) float g_cacheH[B_ * CSLOT * H_];
__device__ __align__(16) float g_cacheC[B_ * CSLOT * H_];
__device__ float g_logit[B_ * CSLOT];
__device__ int4  g_tasks[2 * B_];
__device__ int   g_newSlot[B_];
__device__ int   g_slotOf[B_ * L_];
__device__ int   g_cidx[B_ * L_];
__device__ int2  g_mlist[1024];
__device__ int   g_mcount;
__device__ unsigned g_barCnt[64];

__device__ __forceinline__ float sigm(float x) { return 1.f / (1.f + expf(-x)); }

#define FFMA2(d, a, b) asm("fma.rn.f32x2 %0, %1, %2, %0;" : "+l"(d) : "l"(a), "l"(b))
__device__ __forceinline__ u64 pk2(float lo, float hi) {
    u64 r; asm("mov.b64 %0, {%1, %2};" : "=l"(r) : "f"(lo), "f"(hi)); return r;
}
__device__ __forceinline__ float2 up2(u64 p) {
    float2 r; asm("mov.b64 {%0, %1}, %2;" : "=f"(r.x), "=f"(r.y) : "l"(p)); return r;
}

__device__ __forceinline__ void gridBar(int id) {
    __syncthreads();
    if (threadIdx.x == 0) {
        __threadfence();
        atomicAdd(&g_barCnt[id], 1u);
        while (*(volatile unsigned*)&g_barCnt[id] < (unsigned)NCTA) {}
        __threadfence();
    }
    __syncthreads();
}

// ---------------------------------------------------------------------------
__global__ void kInit(const int* __restrict__ len) {
    int t = blockIdx.x * blockDim.x + threadIdx.x;   // 4096 threads
    if (t < 64) g_barCnt[t] = 0u;
    if (t < B_ * L_) {
        int p = t % L_;
        g_slotOf[t] = p;
        g_cidx[t]   = (p < L_ - 1) ? p : DSLOT;
    }
    if (t < B_) g_logit[t * CSLOT + DSLOT] = 0.f;
    if (blockIdx.x == 0 && threadIdx.x < B_) {
        // compacted u-row list: slots 0..min(lb,31) per batch (slot lb is the
        // single garbage leaf any consumer reads).
        int b = threadIdx.x, off = 0;
        for (int j = 0; j < b; j++) {
            int c = len[j] + 1; if (c > 32) c = 32; off += c;
        }
        int c = len[b] + 1; if (c > 32) c = 32;
        for (int j = 0; j < c; j++) g_mlist[off + j] = make_int2(b, j);
        if (b == B_ - 1) g_mcount = off + c;
    }
    for (int i = t; i < B_ * H_; i += 4096) {
        int b = i / H_, j = i % H_;
        g_poolH[(b * PSLOT + ZSLOT) * H_ + j] = 0.f;
        g_poolC[(b * PSLOT + ZSLOT) * H_ + j] = 0.f;
        g_cacheH[(b * CSLOT + DSLOT) * H_ + j] = 0.f;
        g_cacheC[(b * CSLOT + DSLOT) * H_ + j] = 0.f;
    }
    for (int i = t; i < B_ * H5_; i += 4096) {
        int b = i / H5_, j = i % H5_;
        g_uL[(b * PSLOT + ZSLOT) * H5_ + j] = 0.f;
        g_uR[(b * PSLOT + ZSLOT) * H5_ + j] = 0.f;
    }
}

// ---------------------------------------------------------------------------
// 32x128 GEMM core, 128 threads, 4 rows x 8 cols per thread (f32x2 packed).
// Small tile -> many CTAs -> latency hidden by CTA-level parallelism.
// aPtr = A-row (m0 + tid/4) base + (tid&3)*4.
// bPtr = W + (tid>>3)*ldb + n0 + (tid&7)*4.
// Xs stride 44 floats: 16B-aligned rows, <=2-way staging conflicts.
// ---------------------------------------------------------------------------
__device__ __forceinline__ void gemm32core(const float* aPtr, const float* bPtr,
                                           int ldb, int K, int tid,
                                           float (*Xs)[44], float (*Ws)[132],
                                           u64 (*acc)[4]) {
    const int ar = tid >> 2, aq = (tid & 3) * 4;
    const int wr = tid >> 3, wj = tid & 7;
    const int ty = tid >> 4, tx = tid & 15;
    float4 xa  = *(const float4*)(aPtr);
    float4 wv0 = *(const float4*)(bPtr);
    float4 wv1 = *(const float4*)(bPtr + 32);
    float4 wv2 = *(const float4*)(bPtr + 64);
    float4 wv3 = *(const float4*)(bPtr + 96);
    for (int k0 = 0; k0 < K; k0 += 16) {
        Xs[aq+0][ar] = xa.x; Xs[aq+1][ar] = xa.y;
        Xs[aq+2][ar] = xa.z; Xs[aq+3][ar] = xa.w;
        *(float4*)&Ws[wr][wj*4     ] = wv0;
        *(float4*)&Ws[wr][wj*4 + 32] = wv1;
        *(float4*)&Ws[wr][wj*4 + 64] = wv2;
        *(float4*)&Ws[wr][wj*4 + 96] = wv3;
        __syncthreads();
        if (k0 + 16 < K) {
            xa = *(const float4*)(aPtr + k0 + 16);
            const float* bn = bPtr + (k0 + 16) * ldb;
            wv0 = *(const float4*)(bn);
            wv1 = *(const float4*)(bn + 32);
            wv2 = *(const float4*)(bn + 64);
            wv3 = *(const float4*)(bn + 96);
        }
#pragma unroll
        for (int kk = 0; kk < 16; kk++) {
            float4 a = *(const float4*)&Xs[kk][ty*4];
            u64 pa0 = pk2(a.x,a.x), pa1 = pk2(a.y,a.y);
            u64 pa2 = pk2(a.z,a.z), pa3 = pk2(a.w,a.w);
            u64 bb0 = *(const u64*)&Ws[kk][tx*2];
            u64 bb1 = *(const u64*)&Ws[kk][32 + tx*2];
            u64 bb2 = *(const u64*)&Ws[kk][64 + tx*2];
            u64 bb3 = *(const u64*)&Ws[kk][96 + tx*2];
            FFMA2(acc[0][0],pa0,bb0); FFMA2(acc[0][1],pa0,bb1); FFMA2(acc[0][2],pa0,bb2); FFMA2(acc[0][3],pa0,bb3);
            FFMA2(acc[1][0],pa1,bb0); FFMA2(acc[1][1],pa1,bb1); FFMA2(acc[1][2],pa1,bb2); FFMA2(acc[1][3],pa1,bb3);
            FFMA2(acc[2][0],pa2,bb0); FFMA2(acc[2][1],pa2,bb1); FFMA2(acc[2][2],pa2,bb2); FFMA2(acc[2][3],pa2,bb3);
            FFMA2(acc[3][0],pa3,bb0); FFMA2(acc[3][1],pa3,bb1); FFMA2(acc[3][2],pa3,bb2); FFMA2(acc[3][3],pa3,bb3);
        }
        __syncthreads();
    }
}

// ---------------------------------------------------------------------------
// Leaf GEMM: hc = inp @ W_word + b_word. M=1024, N=1024, K=512. grid(32,8),128thr.
// ---------------------------------------------------------------------------
__global__ void __launch_bounds__(128) kLeafGemm(const float* __restrict__ inp,
                                                 const float* __restrict__ Ww,
                                                 const float* __restrict__ bw,
                                                 float* __restrict__ nodes) {
    const int m0 = blockIdx.x * 32, n0 = blockIdx.y * 128;
    __shared__ __align__(16) float Xs[16][44];
    __shared__ __align__(16) float Ws[16][132];
    const int tid = threadIdx.x;
    u64 acc[4][4] = {};
    const float* aPtr = inp + (m0 + (tid >> 2)) * D_ + (tid & 3) * 4;
    const float* bPtr = Ww + (tid >> 3) * H2_ + n0 + (tid & 7) * 4;
    gemm32core(aPtr, bPtr, H2_, D_, tid, Xs, Ws, acc);

    const int ty = tid >> 4, tx = tid & 15;
    const int cHalf = (n0 >= H_) ? 1 : 0;
#pragma unroll
    for (int r = 0; r < 4; r++) {
        int m = m0 + ty * 4 + r, b = m / L_, l = m % L_;
#pragma unroll
        for (int p = 0; p < 4; p++) {
            int n = n0 + 32 * p + tx * 2;
            float2 bias = *(const float2*)(bw + n);
            float2 v = up2(acc[r][p]);
            v.x += bias.x; v.y += bias.y;
            if (!cHalf) {
                *(float2*)&g_poolH[(b * PSLOT + l) * H_ + n] = v;
                *(float2*)&nodes[(b * 63 + l) * H_ + n] = v;
            } else {
                *(float2*)&g_poolC[(b * PSLOT + l) * H_ + (n - H_)] = v;
            }
        }
    }
}

// ---------------------------------------------------------------------------
// Compacted front u-GEMM (one half): M=g_mcount rows, N=2560, K=512.
// grid(32, 20), 128 thr; blocks with m0 >= cnt exit immediately.
// ---------------------------------------------------------------------------
__global__ void __launch_bounds__(128) kUGemmHalf(const float* __restrict__ Wc,
                                                  int half) {
    const int cnt = g_mcount;
    const int m0 = blockIdx.x * 32;
    if (m0 >= cnt) return;
    const int nn = blockIdx.y * 128;
    __shared__ __align__(16) float Xs[16][44];
    __shared__ __align__(16) float Ws[16][132];
    __shared__ int2 sRows[32];
    const int tid = threadIdx.x;
    if (tid < 32) {
        int r = m0 + tid; if (r >= cnt) r = cnt - 1;
        sRows[tid] = g_mlist[r];
    }
    __syncthreads();
    u64 acc[4][4] = {};
    int2 me = sRows[tid >> 2];
    const float* aPtr = g_poolH + (me.x * PSLOT + me.y) * H_ + (tid & 3) * 4;
    const float* bPtr = Wc + (half * H_ + (tid >> 3)) * H5_ + nn + (tid & 7) * 4;
    gemm32core(aPtr, bPtr, H5_, H_, tid, Xs, Ws, acc);

    const int ty = tid >> 4, tx = tid & 15;
    float* U = half ? g_uR : g_uL;
#pragma unroll
    for (int r = 0; r < 4; r++) {
        int row = m0 + ty * 4 + r;
        if (row < cnt) {
            int2 e = sRows[ty * 4 + r];
            float* dst = U + (e.x * PSLOT + e.y) * H5_ + nn;
#pragma unroll
            for (int p = 0; p < 4; p++)
                *(float2*)&dst[32 * p + tx * 2] = up2(acc[r][p]);
        }
    }
}

// ---------------------------------------------------------------------------
// Vectorized pair activation: lt in [0,128), each thread does 4 elements.
// ---------------------------------------------------------------------------
__device__ __forceinline__ void actPair4(int b, int ls, int rs, int cs,
                                         const float* __restrict__ bc,
                                         const float* __restrict__ q,
                                         int lt, float* red) {
    const float* ul = g_uL + (b * PSLOT + ls) * H5_;
    const float* ur = g_uR + (b * PSLOT + rs) * H5_;
    const float* cl = g_poolC + (b * PSLOT + ls) * H_;
    const float* cr = g_poolC + (b * PSLOT + rs) * H_;
    float* oh = g_cacheH + (b * CSLOT + cs) * H_;
    float* oc = g_cacheC + (b * CSLOT + cs) * H_;
    int j = lt * 4;
    float G[5][4];
#pragma unroll
    for (int g = 0; g < 5; g++) {
        float4 a = *(const float4*)(ul + g * H_ + j);
        float4 r = *(const float4*)(ur + g * H_ + j);
        float4 c = *(const float4*)(bc + g * H_ + j);
        G[g][0] = a.x + r.x + c.x; G[g][1] = a.y + r.y + c.y;
        G[g][2] = a.z + r.z + c.z; G[g][3] = a.w + r.w + c.w;
    }
    float4 cl4 = *(const float4*)(cl + j);
    float4 cr4 = *(const float4*)(cr + j);
    float4 q4  = *(const float4*)(q + j);
    float clv[4] = {cl4.x, cl4.y, cl4.z, cl4.w};
    float crv[4] = {cr4.x, cr4.y, cr4.z, cr4.w};
    float hv[4], cv[4];
#pragma unroll
    for (int l = 0; l < 4; l++) {
        float c = clv[l] * sigm(G[1][l] + 1.f) + crv[l] * sigm(G[2][l] + 1.f)
                + tanhf(G[3][l]) * sigm(G[0][l]);
        hv[l] = sigm(G[4][l]) * tanhf(c); cv[l] = c;
    }
    *(float4*)(oh + j) = make_float4(hv[0], hv[1], hv[2], hv[3]);
    *(float4*)(oc + j) = make_float4(cv[0], cv[1], cv[2], cv[3]);
    float acc = hv[0]*q4.x + hv[1]*q4.y + hv[2]*q4.z + hv[3]*q4.w;
    for (int o = 16; o > 0; o >>= 1) acc += __shfl_down_sync(0xffffffffu, acc, o);
    if ((lt & 31) == 0) red[lt >> 5] = acc;
    __syncthreads();
    if (lt == 0)
        g_logit[b * CSLOT + cs] = red[0] + red[1] + red[2] + red[3];
}

__global__ void __launch_bounds__(128) kAct0(const int* __restrict__ len,
                                             const float* __restrict__ bc,
                                             const float* __restrict__ q) {
    __shared__ float red[4];
    int b = blockIdx.y, j = blockIdx.x;
    if (j >= len[b] - 1) return;
    actPair4(b, j, j + 1, j, bc, q, threadIdx.x, red);
}

// ---------------------------------------------------------------------------
// Select for batch b at step stepI; zeroes the merge slot's u for the next
// step's atomic split-K accumulation.
// ---------------------------------------------------------------------------
__device__ void doSelect(int b, int stepI, const int* __restrict__ len,
                         float* __restrict__ nodes, float* __restrict__ hf,
                         float* __restrict__ cf,
                         int* sPos, int* sPair, int* sKp) {
    int t = threadIdx.x;
    if (t < 32) sPos[t] = g_slotOf[b * L_ + t];
    if (t < 31) sPair[t] = g_cidx[b * L_ + t];
    __syncthreads();
    int lb = len[b];
    if (stepI < lb - 1) {
        if (t == 0) {
            int cand = lb - 1 - stepI, k = 0;
            float best = -1e30f;
            for (int j = 0; j < cand; j++) {
                float v = g_logit[b * CSLOT + sPair[j]];
                if (v > best) { best = v; k = j; }
            }
            *sKp = k;
        }
        __syncthreads();
        int k = *sKp, cs = sPair[k], mslot = 32 + stepI;
        const float* ch = &g_cacheH[(b * CSLOT + cs) * H_];
        const float* cc = &g_cacheC[(b * CSLOT + cs) * H_];
        float* ph = &g_poolH[(b * PSLOT + mslot) * H_];
        float* pc = &g_poolC[(b * PSLOT + mslot) * H_];
        float* nd = &nodes[(b * 63 + 32 + stepI) * H_];
        for (int j = t; j < H_; j += blockDim.x) {
            float hvv = ch[j], cvv = cc[j];
            ph[j] = hvv; pc[j] = cvv; nd[j] = hvv;
            if (stepI == L_ - 2) { hf[b * H_ + j] = hvv; cf[b * H_ + j] = cvv; }
        }
        {
            float4 z = make_float4(0.f, 0.f, 0.f, 0.f);
            float* zl = g_uL + (b * PSLOT + mslot) * H5_;
            float* zr = g_uR + (b * PSLOT + mslot) * H5_;
            for (int j = t * 4; j < H5_; j += blockDim.x * 4) {
                *(float4*)(zl + j) = z;
                *(float4*)(zr + j) = z;
            }
        }
        if (t < 32) {
            int np = (t < k) ? sPos[t] : (t == k) ? mslot : (t < 31) ? sPos[t + 1] : ZSLOT;
            g_slotOf[b * L_ + t] = np;
        }
        if (t < 31) {
            int np;
            if      (t <  k - 1) np = sPair[t];
            else if (t == k - 1) np = 31 + 2 * stepI;
            else if (t == k)     np = 32 + 2 * stepI;
            else if (t < 30)     np = sPair[t + 1];
            else                 np = DSLOT;
            g_cidx[b * L_ + t] = np;
        }
        if (t == 0) {
            int A = 31 + 2 * stepI, Bc = 32 + 2 * stepI;
            g_tasks[2 * b] = (k > 0) ? make_int4(b, sPos[k - 1], mslot, A)
                                     : make_int4(b, ZSLOT, ZSLOT, DSLOT);
            int r = (k + 2 <= 31) ? sPos[k + 2] : ZSLOT;
            g_tasks[2 * b + 1] = make_int4(b, mslot, r, Bc);
            g_newSlot[b] = mslot;
        }
    } else {
        float* nd = &nodes[(b * 63 + 32 + stepI) * H_];
        if (stepI == L_ - 2) {
            int rs = sPos[0];
            const float* ph = &g_poolH[(b * PSLOT + rs) * H_];
            const float* pc = &g_poolC[(b * PSLOT + rs) * H_];
            for (int j = t; j < H_; j += blockDim.x) {
                float hvv = ph[j];
                nd[j] = hvv; hf[b * H_ + j] = hvv; cf[b * H_ + j] = pc[j];
            }
        } else {
            int cs = sPair[0];
            const float* ch = &g_cacheH[(b * CSLOT + cs) * H_];
            for (int j = t; j < H_; j += blockDim.x) nd[j] = ch[j];
        }
        if (t == 0) {
            g_tasks[2 * b]     = make_int4(b, ZSLOT, ZSLOT, DSLOT);
            g_tasks[2 * b + 1] = make_int4(b, ZSLOT, ZSLOT, DSLOT);
            g_newSlot[b] = ZSLOT;
        }
    }
    __syncthreads();
}

// ---------------------------------------------------------------------------
// Step-0 select only. One CTA per batch.
// ---------------------------------------------------------------------------
__global__ void __launch_bounds__(256) kSel0(const int* __restrict__ len,
                                             float* __restrict__ nodes,
                                             float* __restrict__ hf,
                                             float* __restrict__ cf) {
    __shared__ int sPos[32], sPair[31], sK;
    doSelect(blockIdx.x, 0, len, nodes, hf, cf, sPos, sPair, &sK);
}

// ---------------------------------------------------------------------------
// Fused step kernel (R8-proven): phase1 u-GEMM (grid (80,2), M=32, N=5120,
// K split 2, fp32 atomicAdd = exactly-2-way commutative sum), 160-CTA
// barrier, phase2 act + select on CTAs (x<32, y==0).
// ---------------------------------------------------------------------------
__global__ void __launch_bounds__(256) kStep(const int* __restrict__ len,
                                             const float* __restrict__ Wc,
                                             const float* __restrict__ bc,
                                             const float* __restrict__ q,
                                             float* __restrict__ nodes,
                                             float* __restrict__ hf,
                                             float* __restrict__ cf,
                                             int stepI) {
    const int n0g = blockIdx.x * 64;
    const int half = (n0g >= H5_) ? 1 : 0;
    const int nn = n0g - half * H5_;
    const int kb = blockIdx.y * 256;
    __shared__ __align__(16) float As[16][36];
    __shared__ __align__(16) float Ws[16][68];
    __shared__ int sSlot[32];
    __shared__ int sPos[32], sPair[31], sK;
    __shared__ float red[8];
    const int tid = threadIdx.x;
    if (tid < B_) sSlot[tid] = g_newSlot[tid];
    __syncthreads();

    {   // ---- phase 1: u-GEMM
        const int mS = tid >> 2, qS = tid & 3;     // staging (tid<128): rows 0..31
        const int mg = tid >> 4, tx = tid & 15;    // compute: 2 rows, 2 col-pairs
        const float* aPtr = (tid < 128)
            ? g_poolH + (mS * PSLOT + sSlot[mS]) * H_ + kb + qS * 4 : g_poolH;
        const float* bPtr = Wc + (half * H_ + kb + (tid >> 4)) * H5_ + nn + (tid & 15) * 4;
        float4 xr, wv;
        if (tid < 128) xr = *(const float4*)aPtr;
        wv = *(const float4*)bPtr;
        u64 acc[2][2] = {};
        for (int k0 = 0; k0 < 256; k0 += 16) {
            if (tid < 128) {
                As[qS*4+0][mS] = xr.x; As[qS*4+1][mS] = xr.y;
                As[qS*4+2][mS] = xr.z; As[qS*4+3][mS] = xr.w;
            }
            *(float4*)&Ws[tid >> 4][(tid & 15) * 4] = wv;
            __syncthreads();
            if (k0 + 16 < 256) {
                if (tid < 128) xr = *(const float4*)(aPtr + k0 + 16);
                wv = *(const float4*)(bPtr + (k0 + 16) * H5_);
            }
#pragma unroll
            for (int kk = 0; kk < 16; kk++) {
                float a0 = As[kk][mg * 2], a1 = As[kk][mg * 2 + 1];
                u64 b01 = *(const u64*)&Ws[kk][tx*2];
                u64 b23 = *(const u64*)&Ws[kk][32 + tx*2];
                u64 pa0 = pk2(a0, a0), pa1 = pk2(a1, a1);
                FFMA2(acc[0][0], pa0, b01); FFMA2(acc[0][1], pa0, b23);
                FFMA2(acc[1][0], pa1, b01); FFMA2(acc[1][1], pa1, b23);
            }
            __syncthreads();
        }
        float* U = half ? g_uR : g_uL;
#pragma unroll
        for (int e = 0; e < 2; e++) {
            int r = mg * 2 + e;
            float* base = U + (r * PSLOT + sSlot[r]) * H5_ + nn;
            float2 p0 = up2(acc[e][0]), p1 = up2(acc[e][1]);
            atomicAdd(base + tx*2,          p0.x);
            atomicAdd(base + tx*2 + 1,      p0.y);
            atomicAdd(base + 32 + tx*2,     p1.x);
            atomicAdd(base + 32 + tx*2 + 1, p1.y);
        }
    }
    gridBar(stepI - 1);
    // ---- phase 2: act + select (32 CTAs)
    if (blockIdx.y == 0 && blockIdx.x < B_) {
        int b = blockIdx.x;
        int4 tk = (tid < 128) ? g_tasks[2 * b] : g_tasks[2 * b + 1];
        actPair4(b, tk.y, tk.z, tk.w, bc, q, tid & 127, red + ((tid >> 7) << 2));
        __syncthreads();
        doSelect(b, stepI, len, nodes, hf, cf, sPos, sPair, &sK);
    }
}

// ---------------------------------------------------------------------------
extern "C" void kernel_launch(void* const* d_in, const int* in_sizes, int n_in,
                              void* d_out, int out_size) {
    const float* inp = (const float*)d_in[0];
    const int*   len = (const int*)  d_in[1];
    const float* Ww  = (const float*)d_in[2];
    const float* bw  = (const float*)d_in[3];
    const float* Wc  = (const float*)d_in[4];
    const float* bc  = (const float*)d_in[5];
    const float* q   = (const float*)d_in[6];
    float* out   = (float*)d_out;
    float* hf    = out;
    float* cf    = out + B_ * H_;
    float* nodes = out + 2 * B_ * H_;

    kInit<<<16, 256>>>(len);
    kLeafGemm<<<dim3(32, 8), 128>>>(inp, Ww, bw, nodes);
    kUGemmHalf<<<dim3(32, 20), 128>>>(Wc, 0);
    kUGemmHalf<<<dim3(32, 20), 128>>>(Wc, 1);   // <- ncu slot: verify parallelism fix
    kAct0<<<dim3(31, B_), 128>>>(len, bc, q);
    kSel0<<<B_, 256>>>(len, nodes, hf, cf);
    for (int i = 1; i <= L_ - 2; i++)
        kStep<<<dim3(80, 2), 256>>>(len, Wc, bc, q, nodes, hf, cf, i);
}